// round 15
// baseline (speedup 1.0000x reference)
#include <cuda_runtime.h>
#include <cuda_bf16.h>
#include <cuda_fp16.h>
#include <math.h>

#define NMAX 50000
#define EMAX 800000
#define ETOTMAX (NMAX + EMAX)
#define IN_DIM 128
#define HC 256
#define HEADS 4
#define CDIM 64
#define NEG_SLOPE 0.2f
#define SCAN_B 512

// ---------------- scratch ----------------
__device__ __half d_hh[(size_t)NMAX * HC];      // projected features fp16 [N, 256]
__device__ float d_asrc[NMAX * HEADS];
__device__ float d_adst[NMAX * HEADS];
__device__ int4 d_erec[ETOTMAX];                // packed edge record {src, e01h2, e23h2, pad}
__device__ int d_deg[NMAX];
__device__ int d_ptr[NMAX];
__device__ int d_work[NMAX];
__device__ int d_blocksums[SCAN_B];
__device__ int d_blockoff[SCAN_B];
__device__ unsigned d_wfrag[8 * 4 * 32 * 16];   // W pre-swizzled into mma B-fragment order

__device__ __forceinline__ float lrelu(float v) {
    return v > 0.0f ? v : NEG_SLOPE * v;
}

// ---------------- Kernel 0: W -> fp16 B-fragment layout -------------------------
__global__ void convert_w_kernel(const float* __restrict__ W) {
    int idx = blockIdx.x * blockDim.x + threadIdx.x;
    if (idx >= 8 * 4 * 32 * 16) return;
    int q = idx & 15;
    int lane = (idx >> 4) & 31;
    int wn = (idx >> 9) & 3;
    int ki = idx >> 11;
    int ni = q >> 1;
    int reg = q & 1;
    int n = wn * 64 + ni * 8 + (lane >> 2);
    int k = ki * 16 + (lane & 3) * 2 + reg * 8;
    __half2 p = __floats2half2_rn(W[k * HC + n], W[(k + 1) * HC + n]);
    d_wfrag[idx] = *(unsigned*)&p;
}

// ---------------- Kernel 1: fp16 tensor GEMM h = x @ W + fused att epilogue ----
#define GBM 64
__global__ __launch_bounds__(256, 2)
void gemm16_kernel(const float* __restrict__ x,
                   const float* __restrict__ att_src,
                   const float* __restrict__ att_dst, int M) {
    __shared__ __half As[GBM][136];
    __shared__ uint4 Ws[2][640];

    int tid = threadIdx.x;
    int lane = tid & 31;
    int wid = tid >> 5;
    int warp_m = wid & 1;
    int warp_n = wid >> 1;
    int row0 = blockIdx.x * GBM;

    {
        int r = tid >> 2;
        int q = tid & 3;
        int grow = row0 + r;
        const float4* xr = (const float4*)(x + (size_t)grow * IN_DIM);
        #pragma unroll
        for (int j = 0; j < 8; j++) {
            float4 v = make_float4(0.f, 0.f, 0.f, 0.f);
            if (grow < M) v = xr[q * 8 + j];
            __half2 p0 = __floats2half2_rn(v.x, v.y);
            __half2 p1 = __floats2half2_rn(v.z, v.w);
            uint2 u;
            u.x = *(unsigned*)&p0;
            u.y = *(unsigned*)&p1;
            *(uint2*)(&As[r][q * 32 + j * 4]) = u;
        }
    }

    const uint4* wsrc = (const uint4*)d_wfrag;
    {
        int t0 = tid, t1 = tid + 256;
        uint4 p0 = wsrc[t0];
        uint4 p1 = wsrc[t1];
        Ws[0][(t0 >> 2) * 5 + (t0 & 3)] = p0;
        Ws[0][(t1 >> 2) * 5 + (t1 & 3)] = p1;
    }
    __syncthreads();

    float acc[2][8][4];
    #pragma unroll
    for (int mi = 0; mi < 2; mi++)
        #pragma unroll
        for (int ni = 0; ni < 8; ni++)
            #pragma unroll
            for (int c = 0; c < 4; c++) acc[mi][ni][c] = 0.f;

    int mat = lane >> 3;
    int lrow = (mat & 1) * 8 + (lane & 7);
    int lcol = (mat >> 1) * 8;
    int wrow = (warp_n * 32 + lane) * 5;

    #pragma unroll
    for (int ki = 0; ki < 8; ki++) {
        int cur = ki & 1;

        uint4 pf0, pf1;
        if (ki < 7) {
            int base = (ki + 1) * 512;
            pf0 = wsrc[base + tid];
            pf1 = wsrc[base + tid + 256];
        }

        unsigned b[16];
        #pragma unroll
        for (int j = 0; j < 4; j++) {
            uint4 v = Ws[cur][wrow + j];
            b[j * 4 + 0] = v.x; b[j * 4 + 1] = v.y;
            b[j * 4 + 2] = v.z; b[j * 4 + 3] = v.w;
        }
        unsigned a[2][4];
        #pragma unroll
        for (int mi = 0; mi < 2; mi++) {
            int r = warp_m * 32 + mi * 16 + lrow;
            unsigned addr = (unsigned)__cvta_generic_to_shared(&As[r][ki * 16 + lcol]);
            asm volatile("ldmatrix.sync.aligned.m8n8.x4.shared.b16 {%0,%1,%2,%3}, [%4];"
                         : "=r"(a[mi][0]), "=r"(a[mi][1]), "=r"(a[mi][2]), "=r"(a[mi][3])
                         : "r"(addr));
        }
        #pragma unroll
        for (int mi = 0; mi < 2; mi++)
            #pragma unroll
            for (int ni = 0; ni < 8; ni++)
                asm volatile(
                    "mma.sync.aligned.m16n8k16.row.col.f32.f16.f16.f32 "
                    "{%0,%1,%2,%3}, {%4,%5,%6,%7}, {%8,%9}, {%0,%1,%2,%3};"
                    : "+f"(acc[mi][ni][0]), "+f"(acc[mi][ni][1]),
                      "+f"(acc[mi][ni][2]), "+f"(acc[mi][ni][3])
                    : "r"(a[mi][0]), "r"(a[mi][1]), "r"(a[mi][2]), "r"(a[mi][3]),
                      "r"(b[ni * 2]), "r"(b[ni * 2 + 1]));

        if (ki < 7) {
            int nb = cur ^ 1;
            Ws[nb][(tid >> 2) * 5 + (tid & 3)] = pf0;
            Ws[nb][((tid + 256) >> 2) * 5 + ((tid + 256) & 3)] = pf1;
            __syncthreads();
        }
    }

    int g = lane >> 2;
    int tg = lane & 3;
    int head = warp_n;

    float sw[16], dwt[16];
    #pragma unroll
    for (int ni = 0; ni < 8; ni++) {
        int c0 = ni * 8 + tg * 2;
        sw[ni * 2]      = __ldg(&att_src[head * CDIM + c0]);
        sw[ni * 2 + 1]  = __ldg(&att_src[head * CDIM + c0 + 1]);
        dwt[ni * 2]     = __ldg(&att_dst[head * CDIM + c0]);
        dwt[ni * 2 + 1] = __ldg(&att_dst[head * CDIM + c0 + 1]);
    }

    #pragma unroll
    for (int mi = 0; mi < 2; mi++) {
        int ra = row0 + warp_m * 32 + mi * 16 + g;
        int rb = ra + 8;
        float s0 = 0.f, s1 = 0.f, d0 = 0.f, d1 = 0.f;
        #pragma unroll
        for (int ni = 0; ni < 8; ni++) {
            s0 += acc[mi][ni][0] * sw[ni * 2] + acc[mi][ni][1] * sw[ni * 2 + 1];
            s1 += acc[mi][ni][2] * sw[ni * 2] + acc[mi][ni][3] * sw[ni * 2 + 1];
            d0 += acc[mi][ni][0] * dwt[ni * 2] + acc[mi][ni][1] * dwt[ni * 2 + 1];
            d1 += acc[mi][ni][2] * dwt[ni * 2] + acc[mi][ni][3] * dwt[ni * 2 + 1];
            __half2 lo = __floats2half2_rn(acc[mi][ni][0], acc[mi][ni][1]);
            __half2 hi = __floats2half2_rn(acc[mi][ni][2], acc[mi][ni][3]);
            int col = head * CDIM + ni * 8 + tg * 2;
            if (ra < M) *(unsigned*)(d_hh + (size_t)ra * HC + col) = *(unsigned*)&lo;
            if (rb < M) *(unsigned*)(d_hh + (size_t)rb * HC + col) = *(unsigned*)&hi;
        }
        #pragma unroll
        for (int o = 1; o < 4; o <<= 1) {
            s0 += __shfl_xor_sync(0xFFFFFFFFu, s0, o);
            s1 += __shfl_xor_sync(0xFFFFFFFFu, s1, o);
            d0 += __shfl_xor_sync(0xFFFFFFFFu, d0, o);
            d1 += __shfl_xor_sync(0xFFFFFFFFu, d1, o);
        }
        if (tg == 0) {
            if (ra < M) {
                d_asrc[ra * HEADS + head] = s0;
                d_adst[ra * HEADS + head] = d0;
            }
            if (rb < M) {
                d_asrc[rb * HEADS + head] = s1;
                d_adst[rb * HEADS + head] = d1;
            }
        }
    }
}

// ---------------- CSR build ------------------------------------------------------
// deg_hist: 4 edges per thread (int4 load), proven in the 115.4us config
__global__ void deg_hist_kernel(const int* __restrict__ ei, int E) {
    int i0 = (blockIdx.x * blockDim.x + threadIdx.x) * 4;
    if (i0 + 3 < E) {
        int4 d4 = *(const int4*)(ei + E + i0);
        atomicAdd(&d_deg[d4.x], 1);
        atomicAdd(&d_deg[d4.y], 1);
        atomicAdd(&d_deg[d4.z], 1);
        atomicAdd(&d_deg[d4.w], 1);
    } else {
        for (int j = 0; j < 4; j++)
            if (i0 + j < E) atomicAdd(&d_deg[ei[E + i0 + j]], 1);
    }
}

// scan1: warp-shuffle scan (2 barriers); folds self-loop (+1), writes final deg
__global__ void scan1_kernel(int N) {
    __shared__ int wsum[16];
    int b = blockIdx.x, t = threadIdx.x;
    int lane = t & 31, wp = t >> 5;
    int i = b * SCAN_B + t;
    int v = (i < N) ? d_deg[i] + 1 : 0;
    int incl = v;
    #pragma unroll
    for (int o = 1; o < 32; o <<= 1) {
        int xv = __shfl_up_sync(0xFFFFFFFFu, incl, o);
        if (lane >= o) incl += xv;
    }
    if (lane == 31) wsum[wp] = incl;
    __syncthreads();
    if (wp == 0) {
        int s = (lane < 16) ? wsum[lane] : 0;
        #pragma unroll
        for (int o = 1; o < 16; o <<= 1) {
            int xv = __shfl_up_sync(0xFFFFFFFFu, s, o);
            if (lane >= o) s += xv;
        }
        if (lane < 16) wsum[lane] = s;
    }
    __syncthreads();
    int off = (wp > 0) ? wsum[wp - 1] : 0;
    incl += off;
    if (i < N) {
        d_ptr[i] = incl - v;     // exclusive
        d_deg[i] = v;            // final degree incl. self loop
    }
    if (t == SCAN_B - 1) d_blocksums[b] = incl;
}

__global__ void scan2_kernel(int nblocks) {
    __shared__ int wsum[16];
    int t = threadIdx.x;
    int lane = t & 31, wp = t >> 5;
    int v = (t < nblocks) ? d_blocksums[t] : 0;
    int incl = v;
    #pragma unroll
    for (int o = 1; o < 32; o <<= 1) {
        int xv = __shfl_up_sync(0xFFFFFFFFu, incl, o);
        if (lane >= o) incl += xv;
    }
    if (lane == 31) wsum[wp] = incl;
    __syncthreads();
    if (wp == 0) {
        int s = (lane < 16) ? wsum[lane] : 0;
        #pragma unroll
        for (int o = 1; o < 16; o <<= 1) {
            int xv = __shfl_up_sync(0xFFFFFFFFu, s, o);
            if (lane >= o) s += xv;
        }
        if (lane < 16) wsum[lane] = s;
    }
    __syncthreads();
    int off = (wp > 0) ? wsum[wp - 1] : 0;
    if (t < nblocks) d_blockoff[t] = incl + off - v;
}

__global__ void scan3_kernel(int N) {
    int i = blockIdx.x * blockDim.x + threadIdx.x;
    if (i < N) {
        int p = d_ptr[i] + d_blockoff[i / SCAN_B];
        d_ptr[i] = p;
        d_work[i] = p;
    }
}

// fill packed edge records: {src, e01 fp16x2, e23 fp16x2, 0}
__global__ void fill_kernel(const int* __restrict__ ei, int E, int N) {
    int i = blockIdx.x * blockDim.x + threadIdx.x;
    int Etot = E + N;
    if (i >= Etot) return;
    int s, d;
    if (i < E) { s = ei[i]; d = ei[E + i]; } else { s = d = i - E; }
    int pos = atomicAdd(&d_work[d], 1);
    float4 as = *(const float4*)(d_asrc + s * HEADS);
    float4 ad = *(const float4*)(d_adst + d * HEADS);
    __half2 e01 = __floats2half2_rn(__expf(lrelu(as.x + ad.x)), __expf(lrelu(as.y + ad.y)));
    __half2 e23 = __floats2half2_rn(__expf(lrelu(as.z + ad.z)), __expf(lrelu(as.w + ad.w)));
    int4 rec;
    rec.x = s;
    rec.y = *(int*)&e01;
    rec.z = *(int*)&e23;
    rec.w = 0;
    d_erec[pos] = rec;
}

// ---------------- fused softmax + aggregate (warp per node, r12 proven form) -----
__device__ __forceinline__ void agg_edge(int i, int lane,
                                         float* num_x, float* num_y, float* dn) {
    int4 rec = __ldcs(&d_erec[i]);
    int s = rec.x;
    float2 e01 = __half22float2(*(__half2*)&rec.y);
    float2 e23 = __half22float2(*(__half2*)&rec.z);
    const __half2* hs = (const __half2*)(d_hh + (size_t)s * HC);
    float2 f0 = __half22float2(hs[lane]);
    float2 f1 = __half22float2(hs[32 + lane]);
    float2 f2 = __half22float2(hs[64 + lane]);
    float2 f3 = __half22float2(hs[96 + lane]);
    num_x[0] += e01.x * f0.x;  num_y[0] += e01.x * f0.y;
    num_x[1] += e01.y * f1.x;  num_y[1] += e01.y * f1.y;
    num_x[2] += e23.x * f2.x;  num_y[2] += e23.x * f2.y;
    num_x[3] += e23.y * f3.x;  num_y[3] += e23.y * f3.y;
    dn[0] += e01.x; dn[1] += e01.y; dn[2] += e23.x; dn[3] += e23.y;
}

__global__ void aggregate_kernel(const float* __restrict__ bias,
                                 float* __restrict__ out, int N) {
    int w = (blockIdx.x * blockDim.x + threadIdx.x) >> 5;
    int lane = threadIdx.x & 31;
    if (w >= N) return;
    int r0 = d_ptr[w];
    int r1 = r0 + d_deg[w];

    float num_x[4] = {0.f, 0.f, 0.f, 0.f};
    float num_y[4] = {0.f, 0.f, 0.f, 0.f};
    float dn[4] = {0.f, 0.f, 0.f, 0.f};

    int i = r0;
    for (; i + 2 <= r1; i += 2) {
        agg_edge(i, lane, num_x, num_y, dn);
        agg_edge(i + 1, lane, num_x, num_y, dn);
    }
    if (i < r1) agg_edge(i, lane, num_x, num_y, dn);

    float i0 = 1.f / dn[0], i1 = 1.f / dn[1], i2 = 1.f / dn[2], i3 = 1.f / dn[3];
    float vx = (num_x[0] * i0 + num_x[1] * i1 + num_x[2] * i2 + num_x[3] * i3) * 0.25f
             + __ldg(&bias[lane * 2]);
    float vy = (num_y[0] * i0 + num_y[1] * i1 + num_y[2] * i2 + num_y[3] * i3) * 0.25f
             + __ldg(&bias[lane * 2 + 1]);
    float2 o;
    o.x = vx > 0.f ? vx : expm1f(vx);
    o.y = vy > 0.f ? vy : expm1f(vy);
    *(float2*)(out + (size_t)w * CDIM + lane * 2) = o;
}

// ---------------- launch ---------------------------------------------------------
extern "C" void kernel_launch(void* const* d_in, const int* in_sizes, int n_in,
                              void* d_out, int out_size) {
    const float* x       = (const float*)d_in[0];
    const int*   ei      = (const int*)d_in[1];
    const float* W       = (const float*)d_in[2];
    const float* att_src = (const float*)d_in[3];
    const float* att_dst = (const float*)d_in[4];
    const float* bias    = (const float*)d_in[5];
    float* out = (float*)d_out;

    int N = in_sizes[0] / IN_DIM;
    int E = in_sizes[1] / 2;
    int Etot = E + N;
    int nblocks = (N + SCAN_B - 1) / SCAN_B;

    static int* deg_addr = nullptr;
    if (!deg_addr) cudaGetSymbolAddress((void**)&deg_addr, d_deg);

    convert_w_kernel<<<(8 * 4 * 32 * 16 + 255) / 256, 256>>>(W);
    gemm16_kernel<<<(N + GBM - 1) / GBM, 256>>>(x, att_src, att_dst, N);

    cudaMemsetAsync(deg_addr, 0, N * sizeof(int), 0);
    deg_hist_kernel<<<(E / 4 + 255) / 256, 256>>>(ei, E);
    scan1_kernel<<<nblocks, SCAN_B>>>(N);
    scan2_kernel<<<1, SCAN_B>>>(nblocks);
    scan3_kernel<<<(N + 255) / 256, 256>>>(N);
    fill_kernel<<<(Etot + 255) / 256, 256>>>(ei, E, N);

    aggregate_kernel<<<(N * 32 + 255) / 256, 256>>>(bias, out, N);
}

// round 16
// speedup vs baseline: 1.0409x; 1.0409x over previous
#include <cuda_runtime.h>
#include <cuda_bf16.h>
#include <cuda_fp16.h>
#include <math.h>

#define NMAX 50000
#define EMAX 800000
#define ETOTMAX (NMAX + EMAX)
#define IN_DIM 128
#define HC 256
#define HEADS 4
#define CDIM 64
#define NEG_SLOPE 0.2f
#define SCAN_B 512

// ---------------- scratch ----------------
__device__ __half d_hh[(size_t)NMAX * HC];      // projected features fp16 [N, 256]
__device__ float d_asrc[NMAX * HEADS];
__device__ float d_adst[NMAX * HEADS];
__device__ int4 d_erec[ETOTMAX];                // packed edge record {src, e01h2, e23h2, pad}
__device__ int d_deg[NMAX];
__device__ int d_ptr[NMAX];
__device__ int d_work[NMAX];
__device__ int d_blocksums[SCAN_B];
__device__ int d_blockoff[SCAN_B];
__device__ unsigned d_wfrag[8 * 4 * 32 * 16];   // W pre-swizzled into mma B-fragment order

__device__ __forceinline__ float lrelu(float v) {
    return v > 0.0f ? v : NEG_SLOPE * v;
}

// ---------------- Kernel 0: W -> fp16 B-fragment layout -------------------------
__global__ void convert_w_kernel(const float* __restrict__ W) {
    int idx = blockIdx.x * blockDim.x + threadIdx.x;
    if (idx >= 8 * 4 * 32 * 16) return;
    int q = idx & 15;
    int lane = (idx >> 4) & 31;
    int wn = (idx >> 9) & 3;
    int ki = idx >> 11;
    int ni = q >> 1;
    int reg = q & 1;
    int n = wn * 64 + ni * 8 + (lane >> 2);
    int k = ki * 16 + (lane & 3) * 2 + reg * 8;
    __half2 p = __floats2half2_rn(W[k * HC + n], W[(k + 1) * HC + n]);
    d_wfrag[idx] = *(unsigned*)&p;
}

// ---------------- Kernel 1: fp16 tensor GEMM h = x @ W + fused att epilogue ----
#define GBM 64
__global__ __launch_bounds__(256, 2)
void gemm16_kernel(const float* __restrict__ x,
                   const float* __restrict__ att_src,
                   const float* __restrict__ att_dst, int M) {
    __shared__ __half As[GBM][136];
    __shared__ uint4 Ws[2][640];

    int tid = threadIdx.x;
    int lane = tid & 31;
    int wid = tid >> 5;
    int warp_m = wid & 1;
    int warp_n = wid >> 1;
    int row0 = blockIdx.x * GBM;

    {
        int r = tid >> 2;
        int q = tid & 3;
        int grow = row0 + r;
        const float4* xr = (const float4*)(x + (size_t)grow * IN_DIM);
        #pragma unroll
        for (int j = 0; j < 8; j++) {
            float4 v = make_float4(0.f, 0.f, 0.f, 0.f);
            if (grow < M) v = xr[q * 8 + j];
            __half2 p0 = __floats2half2_rn(v.x, v.y);
            __half2 p1 = __floats2half2_rn(v.z, v.w);
            uint2 u;
            u.x = *(unsigned*)&p0;
            u.y = *(unsigned*)&p1;
            *(uint2*)(&As[r][q * 32 + j * 4]) = u;
        }
    }

    const uint4* wsrc = (const uint4*)d_wfrag;
    {
        int t0 = tid, t1 = tid + 256;
        uint4 p0 = wsrc[t0];
        uint4 p1 = wsrc[t1];
        Ws[0][(t0 >> 2) * 5 + (t0 & 3)] = p0;
        Ws[0][(t1 >> 2) * 5 + (t1 & 3)] = p1;
    }
    __syncthreads();

    float acc[2][8][4];
    #pragma unroll
    for (int mi = 0; mi < 2; mi++)
        #pragma unroll
        for (int ni = 0; ni < 8; ni++)
            #pragma unroll
            for (int c = 0; c < 4; c++) acc[mi][ni][c] = 0.f;

    int mat = lane >> 3;
    int lrow = (mat & 1) * 8 + (lane & 7);
    int lcol = (mat >> 1) * 8;
    int wrow = (warp_n * 32 + lane) * 5;

    #pragma unroll
    for (int ki = 0; ki < 8; ki++) {
        int cur = ki & 1;

        uint4 pf0, pf1;
        if (ki < 7) {
            int base = (ki + 1) * 512;
            pf0 = wsrc[base + tid];
            pf1 = wsrc[base + tid + 256];
        }

        unsigned b[16];
        #pragma unroll
        for (int j = 0; j < 4; j++) {
            uint4 v = Ws[cur][wrow + j];
            b[j * 4 + 0] = v.x; b[j * 4 + 1] = v.y;
            b[j * 4 + 2] = v.z; b[j * 4 + 3] = v.w;
        }
        unsigned a[2][4];
        #pragma unroll
        for (int mi = 0; mi < 2; mi++) {
            int r = warp_m * 32 + mi * 16 + lrow;
            unsigned addr = (unsigned)__cvta_generic_to_shared(&As[r][ki * 16 + lcol]);
            asm volatile("ldmatrix.sync.aligned.m8n8.x4.shared.b16 {%0,%1,%2,%3}, [%4];"
                         : "=r"(a[mi][0]), "=r"(a[mi][1]), "=r"(a[mi][2]), "=r"(a[mi][3])
                         : "r"(addr));
        }
        #pragma unroll
        for (int mi = 0; mi < 2; mi++)
            #pragma unroll
            for (int ni = 0; ni < 8; ni++)
                asm volatile(
                    "mma.sync.aligned.m16n8k16.row.col.f32.f16.f16.f32 "
                    "{%0,%1,%2,%3}, {%4,%5,%6,%7}, {%8,%9}, {%0,%1,%2,%3};"
                    : "+f"(acc[mi][ni][0]), "+f"(acc[mi][ni][1]),
                      "+f"(acc[mi][ni][2]), "+f"(acc[mi][ni][3])
                    : "r"(a[mi][0]), "r"(a[mi][1]), "r"(a[mi][2]), "r"(a[mi][3]),
                      "r"(b[ni * 2]), "r"(b[ni * 2 + 1]));

        if (ki < 7) {
            int nb = cur ^ 1;
            Ws[nb][(tid >> 2) * 5 + (tid & 3)] = pf0;
            Ws[nb][((tid + 256) >> 2) * 5 + ((tid + 256) & 3)] = pf1;
            __syncthreads();
        }
    }

    int g = lane >> 2;
    int tg = lane & 3;
    int head = warp_n;

    float sw[16], dwt[16];
    #pragma unroll
    for (int ni = 0; ni < 8; ni++) {
        int c0 = ni * 8 + tg * 2;
        sw[ni * 2]      = __ldg(&att_src[head * CDIM + c0]);
        sw[ni * 2 + 1]  = __ldg(&att_src[head * CDIM + c0 + 1]);
        dwt[ni * 2]     = __ldg(&att_dst[head * CDIM + c0]);
        dwt[ni * 2 + 1] = __ldg(&att_dst[head * CDIM + c0 + 1]);
    }

    #pragma unroll
    for (int mi = 0; mi < 2; mi++) {
        int ra = row0 + warp_m * 32 + mi * 16 + g;
        int rb = ra + 8;
        float s0 = 0.f, s1 = 0.f, d0 = 0.f, d1 = 0.f;
        #pragma unroll
        for (int ni = 0; ni < 8; ni++) {
            s0 += acc[mi][ni][0] * sw[ni * 2] + acc[mi][ni][1] * sw[ni * 2 + 1];
            s1 += acc[mi][ni][2] * sw[ni * 2] + acc[mi][ni][3] * sw[ni * 2 + 1];
            d0 += acc[mi][ni][0] * dwt[ni * 2] + acc[mi][ni][1] * dwt[ni * 2 + 1];
            d1 += acc[mi][ni][2] * dwt[ni * 2] + acc[mi][ni][3] * dwt[ni * 2 + 1];
            __half2 lo = __floats2half2_rn(acc[mi][ni][0], acc[mi][ni][1]);
            __half2 hi = __floats2half2_rn(acc[mi][ni][2], acc[mi][ni][3]);
            int col = head * CDIM + ni * 8 + tg * 2;
            if (ra < M) *(unsigned*)(d_hh + (size_t)ra * HC + col) = *(unsigned*)&lo;
            if (rb < M) *(unsigned*)(d_hh + (size_t)rb * HC + col) = *(unsigned*)&hi;
        }
        #pragma unroll
        for (int o = 1; o < 4; o <<= 1) {
            s0 += __shfl_xor_sync(0xFFFFFFFFu, s0, o);
            s1 += __shfl_xor_sync(0xFFFFFFFFu, s1, o);
            d0 += __shfl_xor_sync(0xFFFFFFFFu, d0, o);
            d1 += __shfl_xor_sync(0xFFFFFFFFu, d1, o);
        }
        if (tg == 0) {
            if (ra < M) {
                d_asrc[ra * HEADS + head] = s0;
                d_adst[ra * HEADS + head] = d0;
            }
            if (rb < M) {
                d_asrc[rb * HEADS + head] = s1;
                d_adst[rb * HEADS + head] = d1;
            }
        }
    }
}

// ---------------- CSR build ------------------------------------------------------
__global__ void deg_hist_kernel(const int* __restrict__ ei, int E) {
    int i0 = (blockIdx.x * blockDim.x + threadIdx.x) * 4;
    if (i0 + 3 < E) {
        int4 d4 = *(const int4*)(ei + E + i0);
        atomicAdd(&d_deg[d4.x], 1);
        atomicAdd(&d_deg[d4.y], 1);
        atomicAdd(&d_deg[d4.z], 1);
        atomicAdd(&d_deg[d4.w], 1);
    } else {
        for (int j = 0; j < 4; j++)
            if (i0 + j < E) atomicAdd(&d_deg[ei[E + i0 + j]], 1);
    }
}

// scan1: warp-shuffle scan; folds self-loop (+1), writes final deg
__global__ void scan1_kernel(int N) {
    __shared__ int wsum[16];
    int b = blockIdx.x, t = threadIdx.x;
    int lane = t & 31, wp = t >> 5;
    int i = b * SCAN_B + t;
    int v = (i < N) ? d_deg[i] + 1 : 0;
    int incl = v;
    #pragma unroll
    for (int o = 1; o < 32; o <<= 1) {
        int xv = __shfl_up_sync(0xFFFFFFFFu, incl, o);
        if (lane >= o) incl += xv;
    }
    if (lane == 31) wsum[wp] = incl;
    __syncthreads();
    if (wp == 0) {
        int s = (lane < 16) ? wsum[lane] : 0;
        #pragma unroll
        for (int o = 1; o < 16; o <<= 1) {
            int xv = __shfl_up_sync(0xFFFFFFFFu, s, o);
            if (lane >= o) s += xv;
        }
        if (lane < 16) wsum[lane] = s;
    }
    __syncthreads();
    int off = (wp > 0) ? wsum[wp - 1] : 0;
    incl += off;
    if (i < N) {
        d_ptr[i] = incl - v;     // exclusive
        d_deg[i] = v;            // final degree incl. self loop
    }
    if (t == SCAN_B - 1) d_blocksums[b] = incl;
}

__global__ void scan2_kernel(int nblocks) {
    __shared__ int wsum[16];
    int t = threadIdx.x;
    int lane = t & 31, wp = t >> 5;
    int v = (t < nblocks) ? d_blocksums[t] : 0;
    int incl = v;
    #pragma unroll
    for (int o = 1; o < 32; o <<= 1) {
        int xv = __shfl_up_sync(0xFFFFFFFFu, incl, o);
        if (lane >= o) incl += xv;
    }
    if (lane == 31) wsum[wp] = incl;
    __syncthreads();
    if (wp == 0) {
        int s = (lane < 16) ? wsum[lane] : 0;
        #pragma unroll
        for (int o = 1; o < 16; o <<= 1) {
            int xv = __shfl_up_sync(0xFFFFFFFFu, s, o);
            if (lane >= o) s += xv;
        }
        if (lane < 16) wsum[lane] = s;
    }
    __syncthreads();
    int off = (wp > 0) ? wsum[wp - 1] : 0;
    if (t < nblocks) d_blockoff[t] = incl + off - v;
}

__global__ void scan3_kernel(int N) {
    int i = blockIdx.x * blockDim.x + threadIdx.x;
    if (i < N) {
        int p = d_ptr[i] + d_blockoff[i / SCAN_B];
        d_ptr[i] = p;
        d_work[i] = p;
    }
}

// fill packed edge records: {src, e01 fp16x2, e23 fp16x2, 0}
__global__ void fill_kernel(const int* __restrict__ ei, int E, int N) {
    int i = blockIdx.x * blockDim.x + threadIdx.x;
    int Etot = E + N;
    if (i >= Etot) return;
    int s, d;
    if (i < E) { s = ei[i]; d = ei[E + i]; } else { s = d = i - E; }
    int pos = atomicAdd(&d_work[d], 1);
    float4 as = *(const float4*)(d_asrc + s * HEADS);
    float4 ad = *(const float4*)(d_adst + d * HEADS);
    __half2 e01 = __floats2half2_rn(__expf(lrelu(as.x + ad.x)), __expf(lrelu(as.y + ad.y)));
    __half2 e23 = __floats2half2_rn(__expf(lrelu(as.z + ad.z)), __expf(lrelu(as.w + ad.w)));
    int4 rec;
    rec.x = s;
    rec.y = *(int*)&e01;
    rec.z = *(int*)&e23;
    rec.w = 0;
    d_erec[pos] = rec;
}

// ---------------- fused softmax + aggregate (warp per node) ----------------------
__device__ __forceinline__ void agg_edge(int i, int lane,
                                         float* num_x, float* num_y, float* dn) {
    int4 rec = __ldg(&d_erec[i]);       // default caching: broadcast load stays L1-hot
    int s = rec.x;
    float2 e01 = __half22float2(*(__half2*)&rec.y);
    float2 e23 = __half22float2(*(__half2*)&rec.z);
    const __half2* hs = (const __half2*)(d_hh + (size_t)s * HC);
    float2 f0 = __half22float2(hs[lane]);
    float2 f1 = __half22float2(hs[32 + lane]);
    float2 f2 = __half22float2(hs[64 + lane]);
    float2 f3 = __half22float2(hs[96 + lane]);
    num_x[0] += e01.x * f0.x;  num_y[0] += e01.x * f0.y;
    num_x[1] += e01.y * f1.x;  num_y[1] += e01.y * f1.y;
    num_x[2] += e23.x * f2.x;  num_y[2] += e23.x * f2.y;
    num_x[3] += e23.y * f3.x;  num_y[3] += e23.y * f3.y;
    dn[0] += e01.x; dn[1] += e01.y; dn[2] += e23.x; dn[3] += e23.y;
}

__global__ void aggregate_kernel(const float* __restrict__ bias,
                                 float* __restrict__ out, int N) {
    int w = (blockIdx.x * blockDim.x + threadIdx.x) >> 5;
    int lane = threadIdx.x & 31;
    if (w >= N) return;
    int r0 = d_ptr[w];
    int r1 = r0 + d_deg[w];

    float num_x[4] = {0.f, 0.f, 0.f, 0.f};
    float num_y[4] = {0.f, 0.f, 0.f, 0.f};
    float dn[4] = {0.f, 0.f, 0.f, 0.f};

    int i = r0;
    for (; i + 2 <= r1; i += 2) {
        agg_edge(i, lane, num_x, num_y, dn);
        agg_edge(i + 1, lane, num_x, num_y, dn);
    }
    if (i < r1) agg_edge(i, lane, num_x, num_y, dn);

    float i0 = 1.f / dn[0], i1 = 1.f / dn[1], i2 = 1.f / dn[2], i3 = 1.f / dn[3];
    float vx = (num_x[0] * i0 + num_x[1] * i1 + num_x[2] * i2 + num_x[3] * i3) * 0.25f
             + __ldg(&bias[lane * 2]);
    float vy = (num_y[0] * i0 + num_y[1] * i1 + num_y[2] * i2 + num_y[3] * i3) * 0.25f
             + __ldg(&bias[lane * 2 + 1]);
    float2 o;
    o.x = vx > 0.f ? vx : expm1f(vx);
    o.y = vy > 0.f ? vy : expm1f(vy);
    *(float2*)(out + (size_t)w * CDIM + lane * 2) = o;
}

// ---------------- launch ---------------------------------------------------------
extern "C" void kernel_launch(void* const* d_in, const int* in_sizes, int n_in,
                              void* d_out, int out_size) {
    const float* x       = (const float*)d_in[0];
    const int*   ei      = (const int*)d_in[1];
    const float* W       = (const float*)d_in[2];
    const float* att_src = (const float*)d_in[3];
    const float* att_dst = (const float*)d_in[4];
    const float* bias    = (const float*)d_in[5];
    float* out = (float*)d_out;

    int N = in_sizes[0] / IN_DIM;
    int E = in_sizes[1] / 2;
    int Etot = E + N;
    int nblocks = (N + SCAN_B - 1) / SCAN_B;

    static int* deg_addr = nullptr;
    if (!deg_addr) cudaGetSymbolAddress((void**)&deg_addr, d_deg);

    convert_w_kernel<<<(8 * 4 * 32 * 16 + 255) / 256, 256>>>(W);
    gemm16_kernel<<<(N + GBM - 1) / GBM, 256>>>(x, att_src, att_dst, N);

    cudaMemsetAsync(deg_addr, 0, N * sizeof(int), 0);
    deg_hist_kernel<<<(E / 4 + 255) / 256, 256>>>(ei, E);
    scan1_kernel<<<nblocks, SCAN_B>>>(N);
    scan2_kernel<<<1, SCAN_B>>>(nblocks);
    scan3_kernel<<<(N + 255) / 256, 256>>>(N);
    fill_kernel<<<(Etot + 255) / 256, 256>>>(ei, E, N);

    aggregate_kernel<<<(N * 32 + 255) / 256, 256>>>(bias, out, N);
}

// round 17
// speedup vs baseline: 1.2225x; 1.1744x over previous
#include <cuda_runtime.h>
#include <cuda_bf16.h>
#include <cuda_fp16.h>
#include <math.h>

#define NMAX 50000
#define EMAX 800000
#define ETOTMAX (NMAX + EMAX)
#define IN_DIM 128
#define HC 256
#define HEADS 4
#define CDIM 64
#define NEG_SLOPE 0.2f
#define SCAN_B 512

// ---------------- scratch ----------------
__device__ __half d_hh[(size_t)NMAX * HC];      // projected features fp16 [N, 256]
__device__ float d_asrc[NMAX * HEADS];
__device__ float d_adst[NMAX * HEADS];
__device__ float d_e[(size_t)ETOTMAX * HEADS];  // per-edge exp(logit), CSR order
__device__ int d_deg[NMAX];
__device__ int d_ptr[NMAX];
__device__ int d_work[NMAX];
__device__ int d_csr_src[ETOTMAX];
__device__ int d_blocksums[SCAN_B];
__device__ int d_blockoff[SCAN_B];
__device__ unsigned d_wfrag[8 * 4 * 32 * 16];   // W pre-swizzled into mma B-fragment order

__device__ __forceinline__ float lrelu(float v) {
    return v > 0.0f ? v : NEG_SLOPE * v;
}

// ---------------- Kernel 0: W -> fp16 B-fragment layout -------------------------
__global__ void convert_w_kernel(const float* __restrict__ W) {
    int idx = blockIdx.x * blockDim.x + threadIdx.x;
    if (idx >= 8 * 4 * 32 * 16) return;
    int q = idx & 15;
    int lane = (idx >> 4) & 31;
    int wn = (idx >> 9) & 3;
    int ki = idx >> 11;
    int ni = q >> 1;
    int reg = q & 1;
    int n = wn * 64 + ni * 8 + (lane >> 2);
    int k = ki * 16 + (lane & 3) * 2 + reg * 8;
    __half2 p = __floats2half2_rn(W[k * HC + n], W[(k + 1) * HC + n]);
    d_wfrag[idx] = *(unsigned*)&p;
}

// ---------------- Kernel 1: fp16 tensor GEMM h = x @ W + fused att epilogue ----
#define GBM 64
__global__ __launch_bounds__(256, 2)
void gemm16_kernel(const float* __restrict__ x,
                   const float* __restrict__ att_src,
                   const float* __restrict__ att_dst, int M) {
    __shared__ __half As[GBM][136];
    __shared__ uint4 Ws[2][640];

    int tid = threadIdx.x;
    int lane = tid & 31;
    int wid = tid >> 5;
    int warp_m = wid & 1;
    int warp_n = wid >> 1;
    int row0 = blockIdx.x * GBM;

    {
        int r = tid >> 2;
        int q = tid & 3;
        int grow = row0 + r;
        const float4* xr = (const float4*)(x + (size_t)grow * IN_DIM);
        #pragma unroll
        for (int j = 0; j < 8; j++) {
            float4 v = make_float4(0.f, 0.f, 0.f, 0.f);
            if (grow < M) v = xr[q * 8 + j];
            __half2 p0 = __floats2half2_rn(v.x, v.y);
            __half2 p1 = __floats2half2_rn(v.z, v.w);
            uint2 u;
            u.x = *(unsigned*)&p0;
            u.y = *(unsigned*)&p1;
            *(uint2*)(&As[r][q * 32 + j * 4]) = u;
        }
    }

    const uint4* wsrc = (const uint4*)d_wfrag;
    {
        int t0 = tid, t1 = tid + 256;
        uint4 p0 = wsrc[t0];
        uint4 p1 = wsrc[t1];
        Ws[0][(t0 >> 2) * 5 + (t0 & 3)] = p0;
        Ws[0][(t1 >> 2) * 5 + (t1 & 3)] = p1;
    }
    __syncthreads();

    float acc[2][8][4];
    #pragma unroll
    for (int mi = 0; mi < 2; mi++)
        #pragma unroll
        for (int ni = 0; ni < 8; ni++)
            #pragma unroll
            for (int c = 0; c < 4; c++) acc[mi][ni][c] = 0.f;

    int mat = lane >> 3;
    int lrow = (mat & 1) * 8 + (lane & 7);
    int lcol = (mat >> 1) * 8;
    int wrow = (warp_n * 32 + lane) * 5;

    #pragma unroll
    for (int ki = 0; ki < 8; ki++) {
        int cur = ki & 1;

        uint4 pf0, pf1;
        if (ki < 7) {
            int base = (ki + 1) * 512;
            pf0 = wsrc[base + tid];
            pf1 = wsrc[base + tid + 256];
        }

        unsigned b[16];
        #pragma unroll
        for (int j = 0; j < 4; j++) {
            uint4 v = Ws[cur][wrow + j];
            b[j * 4 + 0] = v.x; b[j * 4 + 1] = v.y;
            b[j * 4 + 2] = v.z; b[j * 4 + 3] = v.w;
        }
        unsigned a[2][4];
        #pragma unroll
        for (int mi = 0; mi < 2; mi++) {
            int r = warp_m * 32 + mi * 16 + lrow;
            unsigned addr = (unsigned)__cvta_generic_to_shared(&As[r][ki * 16 + lcol]);
            asm volatile("ldmatrix.sync.aligned.m8n8.x4.shared.b16 {%0,%1,%2,%3}, [%4];"
                         : "=r"(a[mi][0]), "=r"(a[mi][1]), "=r"(a[mi][2]), "=r"(a[mi][3])
                         : "r"(addr));
        }
        #pragma unroll
        for (int mi = 0; mi < 2; mi++)
            #pragma unroll
            for (int ni = 0; ni < 8; ni++)
                asm volatile(
                    "mma.sync.aligned.m16n8k16.row.col.f32.f16.f16.f32 "
                    "{%0,%1,%2,%3}, {%4,%5,%6,%7}, {%8,%9}, {%0,%1,%2,%3};"
                    : "+f"(acc[mi][ni][0]), "+f"(acc[mi][ni][1]),
                      "+f"(acc[mi][ni][2]), "+f"(acc[mi][ni][3])
                    : "r"(a[mi][0]), "r"(a[mi][1]), "r"(a[mi][2]), "r"(a[mi][3]),
                      "r"(b[ni * 2]), "r"(b[ni * 2 + 1]));

        if (ki < 7) {
            int nb = cur ^ 1;
            Ws[nb][(tid >> 2) * 5 + (tid & 3)] = pf0;
            Ws[nb][((tid + 256) >> 2) * 5 + ((tid + 256) & 3)] = pf1;
            __syncthreads();
        }
    }

    int g = lane >> 2;
    int tg = lane & 3;
    int head = warp_n;

    float sw[16], dwt[16];
    #pragma unroll
    for (int ni = 0; ni < 8; ni++) {
        int c0 = ni * 8 + tg * 2;
        sw[ni * 2]      = __ldg(&att_src[head * CDIM + c0]);
        sw[ni * 2 + 1]  = __ldg(&att_src[head * CDIM + c0 + 1]);
        dwt[ni * 2]     = __ldg(&att_dst[head * CDIM + c0]);
        dwt[ni * 2 + 1] = __ldg(&att_dst[head * CDIM + c0 + 1]);
    }

    #pragma unroll
    for (int mi = 0; mi < 2; mi++) {
        int ra = row0 + warp_m * 32 + mi * 16 + g;
        int rb = ra + 8;
        float s0 = 0.f, s1 = 0.f, d0 = 0.f, d1 = 0.f;
        #pragma unroll
        for (int ni = 0; ni < 8; ni++) {
            s0 += acc[mi][ni][0] * sw[ni * 2] + acc[mi][ni][1] * sw[ni * 2 + 1];
            s1 += acc[mi][ni][2] * sw[ni * 2] + acc[mi][ni][3] * sw[ni * 2 + 1];
            d0 += acc[mi][ni][0] * dwt[ni * 2] + acc[mi][ni][1] * dwt[ni * 2 + 1];
            d1 += acc[mi][ni][2] * dwt[ni * 2] + acc[mi][ni][3] * dwt[ni * 2 + 1];
            __half2 lo = __floats2half2_rn(acc[mi][ni][0], acc[mi][ni][1]);
            __half2 hi = __floats2half2_rn(acc[mi][ni][2], acc[mi][ni][3]);
            int col = head * CDIM + ni * 8 + tg * 2;
            if (ra < M) *(unsigned*)(d_hh + (size_t)ra * HC + col) = *(unsigned*)&lo;
            if (rb < M) *(unsigned*)(d_hh + (size_t)rb * HC + col) = *(unsigned*)&hi;
        }
        #pragma unroll
        for (int o = 1; o < 4; o <<= 1) {
            s0 += __shfl_xor_sync(0xFFFFFFFFu, s0, o);
            s1 += __shfl_xor_sync(0xFFFFFFFFu, s1, o);
            d0 += __shfl_xor_sync(0xFFFFFFFFu, d0, o);
            d1 += __shfl_xor_sync(0xFFFFFFFFu, d1, o);
        }
        if (tg == 0) {
            if (ra < M) {
                d_asrc[ra * HEADS + head] = s0;
                d_adst[ra * HEADS + head] = d0;
            }
            if (rb < M) {
                d_asrc[rb * HEADS + head] = s1;
                d_adst[rb * HEADS + head] = d1;
            }
        }
    }
}

// ---------------- CSR build ------------------------------------------------------
__global__ void deg_hist_kernel(const int* __restrict__ ei, int E) {
    int i0 = (blockIdx.x * blockDim.x + threadIdx.x) * 4;
    if (i0 + 3 < E) {
        int4 d4 = *(const int4*)(ei + E + i0);
        atomicAdd(&d_deg[d4.x], 1);
        atomicAdd(&d_deg[d4.y], 1);
        atomicAdd(&d_deg[d4.z], 1);
        atomicAdd(&d_deg[d4.w], 1);
    } else {
        for (int j = 0; j < 4; j++)
            if (i0 + j < E) atomicAdd(&d_deg[ei[E + i0 + j]], 1);
    }
}

// scan1: warp-shuffle scan; folds self-loop (+1), writes final deg
__global__ void scan1_kernel(int N) {
    __shared__ int wsum[16];
    int b = blockIdx.x, t = threadIdx.x;
    int lane = t & 31, wp = t >> 5;
    int i = b * SCAN_B + t;
    int v = (i < N) ? d_deg[i] + 1 : 0;
    int incl = v;
    #pragma unroll
    for (int o = 1; o < 32; o <<= 1) {
        int xv = __shfl_up_sync(0xFFFFFFFFu, incl, o);
        if (lane >= o) incl += xv;
    }
    if (lane == 31) wsum[wp] = incl;
    __syncthreads();
    if (wp == 0) {
        int s = (lane < 16) ? wsum[lane] : 0;
        #pragma unroll
        for (int o = 1; o < 16; o <<= 1) {
            int xv = __shfl_up_sync(0xFFFFFFFFu, s, o);
            if (lane >= o) s += xv;
        }
        if (lane < 16) wsum[lane] = s;
    }
    __syncthreads();
    int off = (wp > 0) ? wsum[wp - 1] : 0;
    incl += off;
    if (i < N) {
        d_ptr[i] = incl - v;     // exclusive
        d_deg[i] = v;            // final degree incl. self loop
    }
    if (t == SCAN_B - 1) d_blocksums[b] = incl;
}

__global__ void scan2_kernel(int nblocks) {
    __shared__ int wsum[16];
    int t = threadIdx.x;
    int lane = t & 31, wp = t >> 5;
    int v = (t < nblocks) ? d_blocksums[t] : 0;
    int incl = v;
    #pragma unroll
    for (int o = 1; o < 32; o <<= 1) {
        int xv = __shfl_up_sync(0xFFFFFFFFu, incl, o);
        if (lane >= o) incl += xv;
    }
    if (lane == 31) wsum[wp] = incl;
    __syncthreads();
    if (wp == 0) {
        int s = (lane < 16) ? wsum[lane] : 0;
        #pragma unroll
        for (int o = 1; o < 16; o <<= 1) {
            int xv = __shfl_up_sync(0xFFFFFFFFu, s, o);
            if (lane >= o) s += xv;
        }
        if (lane < 16) wsum[lane] = s;
    }
    __syncthreads();
    int off = (wp > 0) ? wsum[wp - 1] : 0;
    if (t < nblocks) d_blockoff[t] = incl + off - v;
}

__global__ void scan3_kernel(int N) {
    int i = blockIdx.x * blockDim.x + threadIdx.x;
    if (i < N) {
        int p = d_ptr[i] + d_blockoff[i / SCAN_B];
        d_ptr[i] = p;
        d_work[i] = p;
    }
}

// fill CSR + per-edge exp(leakyrelu(logit))  (exact r12 form)
__global__ void fill_kernel(const int* __restrict__ ei, int E, int N) {
    int i = blockIdx.x * blockDim.x + threadIdx.x;
    int Etot = E + N;
    if (i >= Etot) return;
    int s, d;
    if (i < E) { s = ei[i]; d = ei[E + i]; } else { s = d = i - E; }
    int pos = atomicAdd(&d_work[d], 1);
    d_csr_src[pos] = s;
    float4 as = *(const float4*)(d_asrc + s * HEADS);
    float4 ad = *(const float4*)(d_adst + d * HEADS);
    float4 ev;
    ev.x = __expf(lrelu(as.x + ad.x));
    ev.y = __expf(lrelu(as.y + ad.y));
    ev.z = __expf(lrelu(as.z + ad.z));
    ev.w = __expf(lrelu(as.w + ad.w));
    *(float4*)(d_e + (size_t)pos * HEADS) = ev;
}

// ---------------- fused softmax + aggregate (warp per node, r12 proven form) -----
__device__ __forceinline__ void agg_body(int i, int s, int lane,
                                         float* num_x, float* num_y, float* dn) {
    float4 e = *(const float4*)(d_e + (size_t)i * HEADS);
    const __half2* hs = (const __half2*)(d_hh + (size_t)s * HC);
    float2 f0 = __half22float2(hs[lane]);
    float2 f1 = __half22float2(hs[32 + lane]);
    float2 f2 = __half22float2(hs[64 + lane]);
    float2 f3 = __half22float2(hs[96 + lane]);
    num_x[0] += e.x * f0.x;  num_y[0] += e.x * f0.y;
    num_x[1] += e.y * f1.x;  num_y[1] += e.y * f1.y;
    num_x[2] += e.z * f2.x;  num_y[2] += e.z * f2.y;
    num_x[3] += e.w * f3.x;  num_y[3] += e.w * f3.y;
    dn[0] += e.x; dn[1] += e.y; dn[2] += e.z; dn[3] += e.w;
}

__global__ void aggregate_kernel(const float* __restrict__ bias,
                                 float* __restrict__ out, int N) {
    int w = (blockIdx.x * blockDim.x + threadIdx.x) >> 5;
    int lane = threadIdx.x & 31;
    if (w >= N) return;
    int r0 = d_ptr[w];
    int r1 = r0 + d_deg[w];

    float num_x[4] = {0.f, 0.f, 0.f, 0.f};
    float num_y[4] = {0.f, 0.f, 0.f, 0.f};
    float dn[4] = {0.f, 0.f, 0.f, 0.f};

    int i = r0;
    // head-peel to even alignment for paired int2 index loads
    if ((i & 1) && i < r1) {
        int s = __ldg(&d_csr_src[i]);
        agg_body(i, s, lane, num_x, num_y, dn);
        i++;
    }
    for (; i + 2 <= r1; i += 2) {
        int2 s2 = *(const int2*)(d_csr_src + i);   // one LDG.64 for two edge indices
        agg_body(i, s2.x, lane, num_x, num_y, dn);
        agg_body(i + 1, s2.y, lane, num_x, num_y, dn);
    }
    if (i < r1) {
        int s = __ldg(&d_csr_src[i]);
        agg_body(i, s, lane, num_x, num_y, dn);
    }

    float i0 = 1.f / dn[0], i1 = 1.f / dn[1], i2 = 1.f / dn[2], i3 = 1.f / dn[3];
    float vx = (num_x[0] * i0 + num_x[1] * i1 + num_x[2] * i2 + num_x[3] * i3) * 0.25f
             + __ldg(&bias[lane * 2]);
    float vy = (num_y[0] * i0 + num_y[1] * i1 + num_y[2] * i2 + num_y[3] * i3) * 0.25f
             + __ldg(&bias[lane * 2 + 1]);
    float2 o;
    o.x = vx > 0.f ? vx : expm1f(vx);
    o.y = vy > 0.f ? vy : expm1f(vy);
    *(float2*)(out + (size_t)w * CDIM + lane * 2) = o;
}

// ---------------- launch ---------------------------------------------------------
extern "C" void kernel_launch(void* const* d_in, const int* in_sizes, int n_in,
                              void* d_out, int out_size) {
    const float* x       = (const float*)d_in[0];
    const int*   ei      = (const int*)d_in[1];
    const float* W       = (const float*)d_in[2];
    const float* att_src = (const float*)d_in[3];
    const float* att_dst = (const float*)d_in[4];
    const float* bias    = (const float*)d_in[5];
    float* out = (float*)d_out;

    int N = in_sizes[0] / IN_DIM;
    int E = in_sizes[1] / 2;
    int Etot = E + N;
    int nblocks = (N + SCAN_B - 1) / SCAN_B;

    static int* deg_addr = nullptr;
    if (!deg_addr) cudaGetSymbolAddress((void**)&deg_addr, d_deg);

    convert_w_kernel<<<(8 * 4 * 32 * 16 + 255) / 256, 256>>>(W);
    gemm16_kernel<<<(N + GBM - 1) / GBM, 256>>>(x, att_src, att_dst, N);

    cudaMemsetAsync(deg_addr, 0, N * sizeof(int), 0);
    deg_hist_kernel<<<(E / 4 + 255) / 256, 256>>>(ei, E);
    scan1_kernel<<<nblocks, SCAN_B>>>(N);
    scan2_kernel<<<1, SCAN_B>>>(nblocks);
    scan3_kernel<<<(N + 255) / 256, 256>>>(N);
    fill_kernel<<<(Etot + 255) / 256, 256>>>(ei, E, N);

    aggregate_kernel<<<(N * 32 + 255) / 256, 256>>>(bias, out, N);
}